// round 12
// baseline (speedup 1.0000x reference)
#include <cuda_runtime.h>
#include <cuda_fp16.h>

// LatentMap, R12: R6 two-phase fused kernel + fp16-staged embeddings.
//
// R11 (bf16) failed rel_err 1.66e-3 > 1e-3. fp16 has 8x lower rounding
// (11-bit vs 8-bit mantissa) -> expected rel_err ~2e-4, and embeddings
// (~N(0,1e-3)) fit fp16's range trivially. Byte savings identical to bf16:
// embedding rows 128B -> 64B, halving the dominant L2->SM traffic term.
//
// Kernel 0 (convert): f32 -> fp16 into 6.4MB __device__ scratch (~3us).
// Kernel 1 (main): R6 structure verbatim; phase-2 gathers 8B/lane (64B rows).

#define IMG 1024
#define EMB 32
#define N_PTS_MAX 100000
#define WARPS_PER_BLOCK 8
#define QUERIES_PER_WARP 32

__device__ __half g_emb[N_PTS_MAX * EMB];

// ------------------------------------------------------------- convert
__global__ void __launch_bounds__(256) convert_kernel(
    const float* __restrict__ embeddings, int n_elems)
{
    const int i = (blockIdx.x * blockDim.x + threadIdx.x) * 4;
    if (i + 3 < n_elems) {
        const float4 v = *(const float4*)&embeddings[i];
        __half2 lo = __floats2half2_rn(v.x, v.y);
        __half2 hi = __floats2half2_rn(v.z, v.w);
        uint2 packed;
        packed.x = *(unsigned int*)&lo;
        packed.y = *(unsigned int*)&hi;
        *(uint2*)&g_emb[i] = packed;
    } else {
        for (int k = i; k < n_elems; ++k)
            g_emb[k] = __float2half_rn(embeddings[k]);
    }
}

// ------------------------------------------------------------- main
__device__ __forceinline__ float4 load_row4_f16(long base, int fq)
{
    // 8 bytes = 4 fp16 features, aligned (fq multiple of 4).
    const uint2 raw = *(const uint2*)&g_emb[base + fq];
    const __half2 lo = *(const __half2*)&raw.x;
    const __half2 hi = *(const __half2*)&raw.y;
    const float2 a = __half22float2(lo);
    const float2 b = __half22float2(hi);
    return make_float4(a.x, a.y, b.x, b.y);
}

__global__ void __launch_bounds__(WARPS_PER_BLOCK * 32, 8) latent_map_kernel(
    const float2* __restrict__ position,      // [N_Q]
    const float2* __restrict__ positions,     // [N_PTS]
    const int4*   __restrict__ neighbor_map,  // [IMG*IMG]
    const float*  __restrict__ harmonics,     // [EMB]
    float*        __restrict__ out,           // [N_Q, EMB]
    int n_q)
{
    __shared__ int4   s_nb[WARPS_PER_BLOCK][QUERIES_PER_WARP];
    __shared__ float4 s_w [WARPS_PER_BLOCK][QUERIES_PER_WARP];

    const int warp = threadIdx.x >> 5;
    const int lane = threadIdx.x & 31;
    const int qbase = (blockIdx.x * WARPS_PER_BLOCK + warp) * QUERIES_PER_WARP;

    const bool full_tile = (qbase + QUERIES_PER_WARP) <= n_q;

    // ---- Phase 1: one query per lane, scalar work done exactly once ----
    {
        const int q = qbase + lane;
        if (full_tile || q < n_q) {
            const float2 p = position[q];
            const int ix = (int)floorf(p.x);
            const int iy = (int)floorf(p.y);
            const int4 nb = neighbor_map[ix * IMG + iy];

            const float2 p0 = positions[nb.x];
            const float2 p1 = positions[nb.y];
            const float2 p2 = positions[nb.z];
            const float2 p3 = positions[nb.w];

            const float fx = (float)ix, fy = (float)iy;
            float dx, dy;
            dx = p0.x - fx; dy = p0.y - fy;
            const float d0 = sqrtf(dx * dx + dy * dy);
            dx = p1.x - fx; dy = p1.y - fy;
            const float d1 = sqrtf(dx * dx + dy * dy);
            dx = p2.x - fx; dy = p2.y - fy;
            const float d2 = sqrtf(dx * dx + dy * dy);
            dx = p3.x - fx; dy = p3.y - fy;
            const float d3 = sqrtf(dx * dx + dy * dy);

            const float rs = 1.0f / (d0 + d1 + d2 + d3 + 1e-8f);
            float4 w;
            w.x = 1.0f - d0 * rs;
            w.y = 1.0f - d1 * rs;
            w.z = 1.0f - d2 * rs;
            w.w = 1.0f - d3 * rs;

            s_nb[warp][lane] = nb;
            s_w [warp][lane] = w;
        }
    }
    __syncwarp();

    // ---- Phase 2: 4 queries per iteration; lane -> (query sub, feature quad)
    const int sub = lane >> 3;        // 0..3
    const int fq  = (lane & 7) * 4;   // 0,4,...,28

    const float4 h4 = *(const float4*)&harmonics[fq];

    if (full_tile) {
        #pragma unroll
        for (int i = 0; i < QUERIES_PER_WARP; i += 4) {
            const int4   nb = s_nb[warp][i + sub];  // LDS.128
            const float4 w  = s_w [warp][i + sub];  // LDS.128

            const float4 e0 = load_row4_f16((long)nb.x * EMB, fq);
            const float4 e1 = load_row4_f16((long)nb.y * EMB, fq);
            const float4 e2 = load_row4_f16((long)nb.z * EMB, fq);
            const float4 e3 = load_row4_f16((long)nb.w * EMB, fq);

            float4 acc;
            acc.x = w.x * e0.x + w.y * e1.x + w.z * e2.x + w.w * e3.x;
            acc.y = w.x * e0.y + w.y * e1.y + w.z * e2.y + w.w * e3.y;
            acc.z = w.x * e0.z + w.y * e1.z + w.z * e2.z + w.w * e3.z;
            acc.w = w.x * e0.w + w.y * e1.w + w.z * e2.w + w.w * e3.w;

            acc.x *= h4.x; acc.y *= h4.y; acc.z *= h4.z; acc.w *= h4.w;

            *(float4*)&out[(long)(qbase + i + sub) * EMB + fq] = acc;
        }
    } else {
        #pragma unroll
        for (int i = 0; i < QUERIES_PER_WARP; i += 4) {
            const int q = qbase + i + sub;
            if (q < n_q) {
                const int4   nb = s_nb[warp][i + sub];
                const float4 w  = s_w [warp][i + sub];

                const float4 e0 = load_row4_f16((long)nb.x * EMB, fq);
                const float4 e1 = load_row4_f16((long)nb.y * EMB, fq);
                const float4 e2 = load_row4_f16((long)nb.z * EMB, fq);
                const float4 e3 = load_row4_f16((long)nb.w * EMB, fq);

                float4 acc;
                acc.x = w.x * e0.x + w.y * e1.x + w.z * e2.x + w.w * e3.x;
                acc.y = w.x * e0.y + w.y * e1.y + w.z * e2.y + w.w * e3.y;
                acc.z = w.x * e0.z + w.y * e1.z + w.z * e2.z + w.w * e3.z;
                acc.w = w.x * e0.w + w.y * e1.w + w.z * e2.w + w.w * e3.w;

                acc.x *= h4.x; acc.y *= h4.y; acc.z *= h4.z; acc.w *= h4.w;

                *(float4*)&out[(long)q * EMB + fq] = acc;
            }
        }
    }
}

extern "C" void kernel_launch(void* const* d_in, const int* in_sizes, int n_in,
                              void* d_out, int out_size)
{
    const float2* position     = (const float2*)d_in[0];
    const float2* positions    = (const float2*)d_in[1];
    const int4*   neighbor_map = (const int4*)d_in[2];
    const float*  embeddings   = (const float*)d_in[3];
    const float*  harmonics    = (const float*)d_in[4];
    float*        out          = (float*)d_out;

    const int n_q = in_sizes[0] / 2;
    int n_emb = in_sizes[3];                       // N_PTS * EMB
    if (n_emb > N_PTS_MAX * EMB) n_emb = N_PTS_MAX * EMB;

    // Kernel 0: stage embeddings as fp16 (per launch; graph-capturable).
    {
        const int block = 256;
        const int grid = (n_emb / 4 + block - 1) / block;
        convert_kernel<<<grid, block>>>(embeddings, n_emb);
    }

    // Kernel 1: fused two-phase main kernel.
    {
        const int queries_per_block = WARPS_PER_BLOCK * QUERIES_PER_WARP; // 256
        const int grid = (n_q + queries_per_block - 1) / queries_per_block;
        latent_map_kernel<<<grid, WARPS_PER_BLOCK * 32>>>(
            position, positions, neighbor_map, harmonics, out, n_q);
    }
}